// round 13
// baseline (speedup 1.0000x reference)
#include <cuda_runtime.h>
#include <cuda_fp16.h>
#include <cstdint>

// Locally-connected 2D via single-pass fp16 mma.sync m16n8k16.
//   out[b,o,y,x] = sum_k patches[b,y,x,k] * W[y,x,o,k] + bias[y,x,o]
// x: [128,3,64,64] f32, W: [60,60,32,75] f32 (k = c*25+kh*5+kw),
// bias: [60,60,32] f32, out: [128,32,60,60] f32.
// Per position: D[128x32] = A[128x75] @ B[75x32], fp16 in, fp32 accum.
// x compact fp16 g_xh[c][h][w][b] (3.1MB, L2-resident). 512 threads:
// warp = (p, m-quarter), 32 acc/thread, 2 CTAs/SM -> 32 warps/SM.
// k zero-padded to 80 in smem (rows 120..127) -> unconditional inner loop.
// R13: fixed pad-zero loop (R12 only zeroed 512 of 544 words -> NaN).

#define RYX  60
#define TX   4
#define NTHR 512
#define SXS  136          // sXh row stride in u16 (128 + 8 pad)

#define SREP_BYTES 69632                   // sRep overlay (8704 float2)
#define BIAS_OFF   SREP_BYTES
#define SMEM_TOTAL (BIAS_OFF + 512)        // 70144

__device__ unsigned short g_xh[3 * 64 * 64 * 128];   // fp16 x, [c][h][w][b]
__device__ uint2          g_wf[3600 * 640];          // [pos][s:5][nt:4][gid:8][tg:4]

// ---------------------------------------------------------------- helpers
__device__ __forceinline__ unsigned smem_u32(const void* p) {
    unsigned a;
    asm("{ .reg .u64 t; cvta.to.shared.u64 t, %1; cvt.u32.u64 %0, t; }" : "=r"(a) : "l"(p));
    return a;
}
__device__ __forceinline__ void cp16(unsigned sm, const void* g) {
    asm volatile("cp.async.cg.shared.global [%0], [%1], 16;"
                 :: "r"(sm), "l"(__cvta_generic_to_global(g)) : "memory");
}
__device__ __forceinline__ void cp_commit_wait() {
    asm volatile("cp.async.commit_group;" ::: "memory");
    asm volatile("cp.async.wait_group 0;" ::: "memory");
}
__device__ __forceinline__ int rcof(int k) {       // sXh row for flat k (pos 0)
    if (k >= 75) return 120 + (k - 75);            // zero-pad rows
    int c = k / 25, r = (k % 25) / 5, w = k % 5;
    return (c * 5 + r) * 8 + w;
}
__device__ __forceinline__ void mma_f16(float* d, const unsigned* a, unsigned b0, unsigned b1) {
    asm volatile(
        "mma.sync.aligned.m16n8k16.row.col.f32.f16.f16.f32 "
        "{%0,%1,%2,%3}, {%4,%5,%6,%7}, {%8,%9}, {%0,%1,%2,%3};"
        : "+f"(d[0]), "+f"(d[1]), "+f"(d[2]), "+f"(d[3])
        : "r"(a[0]), "r"(a[1]), "r"(a[2]), "r"(a[3]), "r"(b0), "r"(b1));
}

// ---------------------------------------------------------------- prep 1: x -> fp16 [c][h][w][b]
__global__ __launch_bounds__(256)
void prep_xh_kernel(const float* __restrict__ x)
{
    __shared__ float tile[32][33];
    const int wt    = blockIdx.x & 1;
    const int btile = blockIdx.x >> 1;
    const int h     = blockIdx.y;
    const int c     = blockIdx.z;
    const int tx = threadIdx.x, ty = threadIdx.y;

    #pragma unroll
    for (int j = 0; j < 4; j++) {
        int b = btile * 32 + ty + j * 8;
        tile[ty + j * 8][tx] =
            x[(((size_t)b * 3 + c) * 64 + h) * 64 + wt * 32 + tx];
    }
    __syncthreads();
    #pragma unroll
    for (int j = 0; j < 4; j++) {
        int w = wt * 32 + ty + j * 8;
        g_xh[(((size_t)c * 64 + h) * 64 + w) * 128 + btile * 32 + tx] =
            __half_as_ushort(__float2half_rn(tile[tx][ty + j * 8]));
    }
}

// ---------------------------------------------------------------- prep 2: W fragments
__global__ __launch_bounds__(256)
void prep_w_kernel(const float* __restrict__ W)
{
    const int pos = blockIdx.x;
    const float* Wg = W + (size_t)pos * (32 * 75);
    uint2* dst = g_wf + (size_t)pos * 640;

    for (int i = threadIdx.x; i < 640; i += 256) {
        int tg  = i & 3;
        int gid = (i >> 2) & 7;
        int nt  = (i >> 5) & 3;
        int s   = i >> 7;
        int o   = nt * 8 + gid;
        int k0  = 16 * s + 2 * tg;

        unsigned r[4];
        #pragma unroll
        for (int j = 0; j < 4; j++) {
            int k = k0 + (j >> 1) * 8 + (j & 1);
            float v = (k < 75) ? Wg[o * 75 + k] : 0.0f;
            r[j] = (unsigned)__half_as_ushort(__float2half_rn(v));
        }
        dst[i] = make_uint2(r[0] | (r[1] << 16), r[2] | (r[3] << 16));
    }
}

// ---------------------------------------------------------------- main
__global__ __launch_bounds__(NTHR, 2)
void lc2d_hmma_kernel(const float* __restrict__ bias,
                      float* __restrict__ out)
{
    extern __shared__ char smem[];
    unsigned short* sXh = (unsigned short*)smem;     // [128 rows][SXS] (120 data + 8 zero)
    float* sBias = (float*)(smem + BIAS_OFF);        // [TX][32]

    const int xt   = blockIdx.x;          // 15
    const int py   = blockIdx.y;          // 60
    const int px0  = xt * TX;
    const int pos0 = py * RYX + px0;
    const int tid  = threadIdx.x;

    const unsigned sXh_a = smem_u32(sXh);

    // thread/warp mapping (needed early for B prefetch)
    const int wid  = tid >> 5;
    const int lane = tid & 31;
    const int gid  = lane >> 2;
    const int tg   = lane & 3;
    const int p    = wid >> 2;          // 0..3
    const int mq   = wid & 3;           // 0..3

    // ---- B-fragment prefetch (gmem, independent of smem stage) ----
    const uint2* wfp = g_wf + (size_t)(pos0 + p) * 640 + gid * 4 + tg;
    uint2 bh[4];
    #pragma unroll
    for (int nt = 0; nt < 4; nt++) bh[nt] = __ldg(wfp + nt * 32);

    // ---- stage x tile: 120 rows x 128 u16, cp.async 16B chunks ----
    for (int i = tid; i < 120 * 16; i += NTHR) {
        int q    = i & 15;
        int rc   = i >> 4;                 // (c*5+kh)*8 + col
        int crow = rc >> 3, col = rc & 7;
        int c = crow / 5, kh = crow - c * 5;
        cp16(sXh_a + (rc * SXS + q * 8) * 2,
             &g_xh[(((size_t)c * 64 + py + kh) * 64 + px0 + col) * 128 + q * 8]);
    }
    // zero-pad rows 120..127 (8 rows x 136 u16 = 544 u32) — full coverage
    for (int i = tid; i < 544; i += NTHR) {
        *reinterpret_cast<unsigned*>(&sXh[120 * SXS + i * 2]) = 0u;
    }
    if (tid < TX * 32) sBias[tid] = bias[pos0 * 32 + tid];
    cp_commit_wait();
    __syncthreads();

    float acc[2][4][4];
    #pragma unroll
    for (int mt = 0; mt < 2; mt++)
        #pragma unroll
        for (int nt = 0; nt < 4; nt++)
            #pragma unroll
            for (int r = 0; r < 4; r++) acc[mt][nt][r] = 0.0f;

    #pragma unroll
    for (int s = 0; s < 5; s++) {
        uint2 bh2[4];
        if (s < 4) {
            #pragma unroll
            for (int nt = 0; nt < 4; nt++)
                bh2[nt] = __ldg(wfp + (s + 1) * 128 + nt * 32);
        }

        // A row offsets (u16 index) for k0, k0+1, k0+8, k0+9 (k padded to 80)
        const int k0 = 16 * s + 2 * tg;
        const int off00 = (rcof(k0)     + p) * SXS;
        const int off01 = (rcof(k0 + 1) + p) * SXS;
        const int off10 = (rcof(k0 + 8) + p) * SXS;
        const int off11 = (rcof(k0 + 9) + p) * SXS;

        #pragma unroll
        for (int mt = 0; mt < 2; mt++) {
            const int b = mq * 32 + mt * 16 + gid;
            unsigned a[4];
            a[0] = (unsigned)sXh[off00 + b]     | ((unsigned)sXh[off01 + b]     << 16);
            a[1] = (unsigned)sXh[off00 + b + 8] | ((unsigned)sXh[off01 + b + 8] << 16);
            a[2] = (unsigned)sXh[off10 + b]     | ((unsigned)sXh[off11 + b]     << 16);
            a[3] = (unsigned)sXh[off10 + b + 8] | ((unsigned)sXh[off11 + b + 8] << 16);

            #pragma unroll
            for (int nt = 0; nt < 4; nt++)
                mma_f16(acc[mt][nt], a, bh[nt].x, bh[nt].y);
        }

        if (s < 4) {
            #pragma unroll
            for (int nt = 0; nt < 4; nt++) bh[nt] = bh2[nt];
        }
    }

    // ---- bias into regs, then overlay stage with repack buffer ----
    float bsv[4][2];
    #pragma unroll
    for (int nt = 0; nt < 4; nt++) {
        bsv[nt][0] = sBias[p * 32 + nt * 8 + 2 * tg];
        bsv[nt][1] = sBias[p * 32 + nt * 8 + 2 * tg + 1];
    }
    __syncthreads();   // sXh dead

    // ---- repack: sRep[px][b][o-pair] float2 ----
    float2* sRep = (float2*)smem;        // [(p*128 + b)*17 + nt*4 + tg]
    #pragma unroll
    for (int mt = 0; mt < 2; mt++) {
        #pragma unroll
        for (int rh = 0; rh < 2; rh++) {
            const int b = mq * 32 + mt * 16 + gid + rh * 8;
            #pragma unroll
            for (int nt = 0; nt < 4; nt++) {
                sRep[(p * 128 + b) * 17 + nt * 4 + tg] =
                    make_float2(acc[mt][nt][rh * 2] + bsv[nt][0],
                                acc[mt][nt][rh * 2 + 1] + bsv[nt][1]);
            }
        }
    }
    __syncthreads();

    // ---- store: float4 over px (16B contiguous) ----
    const float* rf = (const float*)smem;
    for (int j = tid; j < 128 * 32; j += NTHR) {
        int b = j >> 5, o = j & 31;
        float4 v;
        v.x = rf[((0 * 128 + b) * 34) + o];
        v.y = rf[((1 * 128 + b) * 34) + o];
        v.z = rf[((2 * 128 + b) * 34) + o];
        v.w = rf[((3 * 128 + b) * 34) + o];
        *reinterpret_cast<float4*>(&out[((size_t)(b * 32 + o)) * 3600 + pos0]) = v;
    }
}

// ---------------------------------------------------------------- launch
extern "C" void kernel_launch(void* const* d_in, const int* in_sizes, int n_in,
                              void* d_out, int out_size)
{
    const float* x    = (const float*)d_in[0];
    const float* W    = (const float*)d_in[1];
    const float* bias = (const float*)d_in[2];
    float* out        = (float*)d_out;

    cudaFuncSetAttribute(lc2d_hmma_kernel,
                         cudaFuncAttributeMaxDynamicSharedMemorySize, SMEM_TOTAL);

    prep_xh_kernel<<<dim3(8, 64, 3), dim3(32, 8)>>>(x);
    prep_w_kernel<<<3600, 256>>>(W);
    lc2d_hmma_kernel<<<dim3(RYX / TX, RYX), NTHR, SMEM_TOTAL>>>(bias, out);
}

// round 14
// speedup vs baseline: 1.3053x; 1.3053x over previous
#include <cuda_runtime.h>
#include <cuda_fp16.h>
#include <cstdint>

// Locally-connected 2D via single-pass fp16 mma.sync m16n8k16.
//   out[b,o,y,x] = sum_k patches[b,y,x,k] * W[y,x,o,k] + bias[y,x,o]
// x: [128,3,64,64] f32, W: [60,60,32,75] f32 (k = c*25+kh*5+kw),
// bias: [60,60,32] f32, out: [128,32,60,60] f32.
// Per position: D[128x32] = A[128x75] @ B[75x32], fp16 in, fp32 accum.
// R14 = R11 (best: 256 thr, warp=(p,mh), 64 acc, 2 CTAs/SM) with prep_w
// folded into the main kernel: W staged raw f32 via cp.async, B-fragments
// built in-loop with LDS + cvt.rn.f16x2.f32 (bit-identical fragments).

#define RYX  60
#define TX   4
#define NTHR 256
#define SXS  136          // sXh row stride in u16 (128 + 8 pad)

#define SW_OFF     32640                   // sXh = 120*136*2 bytes
#define BIAS_OFF   (SW_OFF + 38400)        // sW = 9600 f32 -> 71040
#define SMEM_TOTAL (BIAS_OFF + 512)        // 71552 (sRep overlay needs 69632 < 71040)

__device__ unsigned short g_xh[3 * 64 * 64 * 128];   // fp16 x, [c][h][w][b]

// ---------------------------------------------------------------- helpers
__device__ __forceinline__ unsigned smem_u32(const void* p) {
    unsigned a;
    asm("{ .reg .u64 t; cvta.to.shared.u64 t, %1; cvt.u32.u64 %0, t; }" : "=r"(a) : "l"(p));
    return a;
}
__device__ __forceinline__ void cp16(unsigned sm, const void* g) {
    asm volatile("cp.async.cg.shared.global [%0], [%1], 16;"
                 :: "r"(sm), "l"(__cvta_generic_to_global(g)) : "memory");
}
__device__ __forceinline__ void cp_commit_wait() {
    asm volatile("cp.async.commit_group;" ::: "memory");
    asm volatile("cp.async.wait_group 0;" ::: "memory");
}
__device__ __forceinline__ int rcof(int k) {       // sXh row for flat k (pos 0)
    int c = k / 25, r = (k % 25) / 5, w = k % 5;
    return (c * 5 + r) * 8 + w;
}
// pack two f32 -> fp16x2; low half = lo, high half = hi (PTX: first src = high)
__device__ __forceinline__ unsigned pack_h2(float hi, float lo) {
    unsigned r;
    asm("cvt.rn.f16x2.f32 %0, %1, %2;" : "=r"(r) : "f"(hi), "f"(lo));
    return r;
}
__device__ __forceinline__ void mma_f16(float* d, const unsigned* a, unsigned b0, unsigned b1) {
    asm volatile(
        "mma.sync.aligned.m16n8k16.row.col.f32.f16.f16.f32 "
        "{%0,%1,%2,%3}, {%4,%5,%6,%7}, {%8,%9}, {%0,%1,%2,%3};"
        : "+f"(d[0]), "+f"(d[1]), "+f"(d[2]), "+f"(d[3])
        : "r"(a[0]), "r"(a[1]), "r"(a[2]), "r"(a[3]), "r"(b0), "r"(b1));
}

// ---------------------------------------------------------------- prep: x -> fp16 [c][h][w][b]
__global__ __launch_bounds__(256)
void prep_xh_kernel(const float* __restrict__ x)
{
    __shared__ float tile[32][33];
    const int wt    = blockIdx.x & 1;
    const int btile = blockIdx.x >> 1;
    const int h     = blockIdx.y;
    const int c     = blockIdx.z;
    const int tx = threadIdx.x, ty = threadIdx.y;

    #pragma unroll
    for (int j = 0; j < 4; j++) {
        int b = btile * 32 + ty + j * 8;
        tile[ty + j * 8][tx] =
            x[(((size_t)b * 3 + c) * 64 + h) * 64 + wt * 32 + tx];
    }
    __syncthreads();
    #pragma unroll
    for (int j = 0; j < 4; j++) {
        int w = wt * 32 + ty + j * 8;
        g_xh[(((size_t)c * 64 + h) * 64 + w) * 128 + btile * 32 + tx] =
            __half_as_ushort(__float2half_rn(tile[tx][ty + j * 8]));
    }
}

// ---------------------------------------------------------------- main
__global__ __launch_bounds__(NTHR, 2)
void lc2d_hmma_kernel(const float* __restrict__ W,
                      const float* __restrict__ bias,
                      float* __restrict__ out)
{
    extern __shared__ char smem[];
    unsigned short* sXh = (unsigned short*)smem;     // [120 rows][SXS]
    const float* sWf    = (const float*)(smem + SW_OFF);   // [128 po][75] raw f32
    float* sBias        = (float*)(smem + BIAS_OFF); // [TX][32]

    const int xt   = blockIdx.x;          // 15
    const int py   = blockIdx.y;          // 60
    const int px0  = xt * TX;
    const int pos0 = py * RYX + px0;
    const int tid  = threadIdx.x;

    const unsigned sXh_a = smem_u32(sXh);
    const unsigned sW_a  = smem_u32(sWf);

    // ---- stage x tile: 120 rows x 128 u16, cp.async 16B chunks ----
    for (int i = tid; i < 120 * 16; i += NTHR) {
        int q    = i & 15;
        int rc   = i >> 4;                 // (c*5+kh)*8 + col
        int crow = rc >> 3, col = rc & 7;
        int c = crow / 5, kh = crow - c * 5;
        cp16(sXh_a + (rc * SXS + q * 8) * 2,
             &g_xh[(((size_t)c * 64 + py + kh) * 64 + px0 + col) * 128 + q * 8]);
    }
    // ---- stage W raw: 9600 f32 contiguous, cp.async ----
    {
        const float* Wg = W + (size_t)pos0 * (32 * 75);
        for (int i = tid; i < 2400; i += NTHR)
            cp16(sW_a + i * 16, Wg + i * 4);
    }
    if (tid < TX * 32) sBias[tid] = bias[pos0 * 32 + tid];
    cp_commit_wait();
    __syncthreads();

    // ---- compute: warp = (position p, m-half mh); 4 m-tiles x 4 n-tiles ----
    const int wid  = tid >> 5;
    const int lane = tid & 31;
    const int gid  = lane >> 2;
    const int tg   = lane & 3;
    const int p    = wid >> 1;          // 0..3
    const int mh   = wid & 1;

    float acc[4][4][4];
    #pragma unroll
    for (int mt = 0; mt < 4; mt++)
        #pragma unroll
        for (int nt = 0; nt < 4; nt++)
            #pragma unroll
            for (int r = 0; r < 4; r++) acc[mt][nt][r] = 0.0f;

    const float* wrow = sWf + (p * 32 + gid) * 75;   // + nt*600 + k

    #pragma unroll
    for (int s = 0; s < 5; s++) {
        const int k0 = 16 * s + 2 * tg;

        // B fragments from raw W: LDS + cvt (bit-identical to prep_w output)
        uint2 bh[4];
        #pragma unroll
        for (int nt = 0; nt < 4; nt++) {
            const float* wr = wrow + nt * 600;
            float f0 = wr[k0];
            float f1 = wr[k0 + 1];
            float f2, f3;
            if (s < 4) {
                f2 = wr[k0 + 8];
                f3 = wr[k0 + 9];
            } else {
                f2 = (k0 + 8 < 75) ? wr[k0 + 8] : 0.0f;
                f3 = (k0 + 9 < 75) ? wr[k0 + 9] : 0.0f;
            }
            bh[nt].x = pack_h2(f1, f0);
            bh[nt].y = pack_h2(f3, f2);
        }

        // A row offsets (u16 index) for k0, k0+1, k0+8, k0+9
        const int off00 = (rcof(k0)     + p) * SXS;
        const int off01 = (rcof(k0 + 1) + p) * SXS;
        const bool v2 = (k0 + 8) < 75;
        const bool v3 = (k0 + 9) < 75;
        const int off10 = v2 ? (rcof(k0 + 8) + p) * SXS : 0;
        const int off11 = v3 ? (rcof(k0 + 9) + p) * SXS : 0;

        #pragma unroll
        for (int mt = 0; mt < 4; mt++) {
            const int b = mh * 64 + mt * 16 + gid;
            unsigned a[4];
            a[0] = (unsigned)sXh[off00 + b]
                 | ((unsigned)sXh[off01 + b] << 16);
            a[1] = (unsigned)sXh[off00 + b + 8]
                 | ((unsigned)sXh[off01 + b + 8] << 16);
            a[2] = (v2 ? (unsigned)sXh[off10 + b] : 0u)
                 | ((v3 ? (unsigned)sXh[off11 + b] : 0u) << 16);
            a[3] = (v2 ? (unsigned)sXh[off10 + b + 8] : 0u)
                 | ((v3 ? (unsigned)sXh[off11 + b + 8] : 0u) << 16);

            #pragma unroll
            for (int nt = 0; nt < 4; nt++)
                mma_f16(acc[mt][nt], a, bh[nt].x, bh[nt].y);
        }
    }

    // ---- bias into regs, then overlay stage with repack buffer ----
    float bsv[4][2];
    #pragma unroll
    for (int nt = 0; nt < 4; nt++) {
        bsv[nt][0] = sBias[p * 32 + nt * 8 + 2 * tg];
        bsv[nt][1] = sBias[p * 32 + nt * 8 + 2 * tg + 1];
    }
    __syncthreads();   // sXh + sW dead

    // ---- repack: sRep[px][b][o-pair] float2 ----
    float2* sRep = (float2*)smem;        // [(p*128 + b)*17 + nt*4 + tg]
    #pragma unroll
    for (int mt = 0; mt < 4; mt++) {
        #pragma unroll
        for (int rh = 0; rh < 2; rh++) {
            const int b = mh * 64 + mt * 16 + gid + rh * 8;
            #pragma unroll
            for (int nt = 0; nt < 4; nt++) {
                sRep[(p * 128 + b) * 17 + nt * 4 + tg] =
                    make_float2(acc[mt][nt][rh * 2] + bsv[nt][0],
                                acc[mt][nt][rh * 2 + 1] + bsv[nt][1]);
            }
        }
    }
    __syncthreads();

    // ---- store: float4 over px (16B contiguous) ----
    const float* rf = (const float*)smem;
    for (int j = tid; j < 128 * 32; j += NTHR) {
        int b = j >> 5, o = j & 31;
        float4 v;
        v.x = rf[((0 * 128 + b) * 34) + o];
        v.y = rf[((1 * 128 + b) * 34) + o];
        v.z = rf[((2 * 128 + b) * 34) + o];
        v.w = rf[((3 * 128 + b) * 34) + o];
        *reinterpret_cast<float4*>(&out[((size_t)(b * 32 + o)) * 3600 + pos0]) = v;
    }
}

// ---------------------------------------------------------------- launch
extern "C" void kernel_launch(void* const* d_in, const int* in_sizes, int n_in,
                              void* d_out, int out_size)
{
    const float* x    = (const float*)d_in[0];
    const float* W    = (const float*)d_in[1];
    const float* bias = (const float*)d_in[2];
    float* out        = (float*)d_out;

    cudaFuncSetAttribute(lc2d_hmma_kernel,
                         cudaFuncAttributeMaxDynamicSharedMemorySize, SMEM_TOTAL);

    prep_xh_kernel<<<dim3(8, 64, 3), dim3(32, 8)>>>(x);
    lc2d_hmma_kernel<<<dim3(RYX / TX, RYX), NTHR, SMEM_TOTAL>>>(W, bias, out);
}